// round 2
// baseline (speedup 1.0000x reference)
#include <cuda_runtime.h>
#include <cuda_bf16.h>
#include <cstdint>

// Problem dims (fixed by the dataset)
#define B   64
#define D   3072
#define NA  4
#define A   2048
#define NN  (NA * A)        // 8192
#define KC  256             // K-chunk held in smem per iteration
#define THRESHOLD 0.02f

// Scratch (static device globals — no allocation allowed)
__device__ float g_gate[NA];
__device__ float g_znew[B * NN];   // 2 MB

// ---------- f32x2 helpers ----------
__device__ __forceinline__ unsigned long long pack2(float lo, float hi) {
    unsigned long long d;
    asm("mov.b64 %0, {%1, %2};" : "=l"(d) : "f"(lo), "f"(hi));
    return d;
}
__device__ __forceinline__ unsigned long long fma2(unsigned long long a,
                                                   unsigned long long b,
                                                   unsigned long long c) {
    unsigned long long d;
    asm("fma.rn.f32x2 %0, %1, %2, %3;" : "=l"(d) : "l"(a), "l"(b), "l"(c));
    return d;
}
__device__ __forceinline__ void unpack2(unsigned long long v, float& lo, float& hi) {
    asm("mov.b64 {%0, %1}, %2;" : "=f"(lo), "=f"(hi) : "l"(v));
}

// ---------- Kernel 1: gate per area ----------
__global__ void gate_kernel(const float* __restrict__ Z) {
    int i = blockIdx.x;            // area
    int t = threadIdx.x;
    float s = 0.f;
    // 64 * 2048 = 131072 elements per area
    for (int idx = t; idx < B * A; idx += 256) {
        int b = idx >> 11;
        int a = idx & (A - 1);
        s += fabsf(Z[(size_t)b * NN + (size_t)i * A + a]);
    }
    __shared__ float red[256];
    red[t] = s;
    __syncthreads();
    for (int st = 128; st > 0; st >>= 1) {
        if (t < st) red[t] += red[t + st];
        __syncthreads();
    }
    if (t == 0)
        g_gate[i] = (red[0] * (1.0f / (float)(B * A)) > THRESHOLD) ? 1.0f : 0.0f;
}

// ---------- Kernel 2: fused einsum + stim + epilogue ----------
// Grid: 128 blocks x 256 threads. Each block owns 64 output columns.
// Thread t: column n = blk*64 + (t & 63), batch-group g = t >> 6 (16 batches).
// Accumulators: 16 x f32x2 (even-k / odd-k partial sums per batch).
__global__ __launch_bounds__(256, 1)
void main_kernel(const float* __restrict__ x,
                 const float* __restrict__ Z,
                 const float* __restrict__ Fstate,
                 const float* __restrict__ rw,       // receptors_w [N, D]
                 const float* __restrict__ rb,       // receptors_b [N]
                 const float* __restrict__ W,        // [NA,NA,A,A]
                 const float* __restrict__ Wmask,    // [NA,NA,A,A]
                 const float* __restrict__ bias_diag)// [NA,A]
{
    __shared__ __align__(16) float zs[B * KC];   // [b][k] layout, 64 KB

    const int t = threadIdx.x;
    const int n = blockIdx.x * 64 + (t & 63);
    const int g = t >> 6;                 // 0..3
    const int o = n >> 11;                // n / A
    const int u = n & (A - 1);            // n % A

    float gates[NA];
#pragma unroll
    for (int i = 0; i < NA; i++) gates[i] = g_gate[i];

    unsigned long long acc[16];
#pragma unroll
    for (int bi = 0; bi < 16; bi++) acc[bi] = 0ULL;

    const float* zrow_base = zs + (size_t)(g * 16) * KC;

    // ================= einsum over K = 8192 =================
    for (int k0 = 0; k0 < NN; k0 += KC) {
        const int i = k0 >> 11;           // area of this whole chunk
        const float gk = gates[i];
        // cooperative load of Z[:, k0:k0+KC] (gated) into zs[b][j]
#pragma unroll
        for (int v = 0; v < 16; v++) {
            int f = t + 256 * v;          // float4 index, 4096 total
            int p = f << 2;
            int b = p >> 8;               // p / KC
            int j = p & (KC - 1);
            float4 zv = *reinterpret_cast<const float4*>(Z + (size_t)b * NN + k0 + j);
            zv.x *= gk; zv.y *= gk; zv.z *= gk; zv.w *= gk;
            *reinterpret_cast<float4*>(zs + (size_t)b * KC + j) = zv;
        }
        __syncthreads();

        const size_t woff = ((size_t)o << 24) + ((size_t)i << 22) +
                            ((size_t)u << 11) + (size_t)(k0 & (A - 1));
        const float* wrow = W + woff;
        const float* mrow = Wmask + woff;

#pragma unroll 4
        for (int k = 0; k < KC; k += 4) {
            float4 wv = *reinterpret_cast<const float4*>(wrow + k);
            float4 mv = *reinterpret_cast<const float4*>(mrow + k);
            unsigned long long wp0 = pack2(wv.x * __saturatef(mv.x),
                                           wv.y * __saturatef(mv.y));
            unsigned long long wp1 = pack2(wv.z * __saturatef(mv.z),
                                           wv.w * __saturatef(mv.w));
#pragma unroll
            for (int bi = 0; bi < 16; bi++) {
                ulonglong2 av = *reinterpret_cast<const ulonglong2*>(
                    zrow_base + (size_t)bi * KC + k);
                acc[bi] = fma2(wp0, av.x, acc[bi]);
                acc[bi] = fma2(wp1, av.y, acc[bi]);
            }
        }
        __syncthreads();
    }

    // ================= stim over K = 3072 =================
    for (int d0 = 0; d0 < D; d0 += KC) {
#pragma unroll
        for (int v = 0; v < 16; v++) {
            int f = t + 256 * v;
            int p = f << 2;
            int b = p >> 8;
            int j = p & (KC - 1);
            float4 xv = *reinterpret_cast<const float4*>(x + (size_t)b * D + d0 + j);
            *reinterpret_cast<float4*>(zs + (size_t)b * KC + j) = xv;
        }
        __syncthreads();

        const float* wrow = rw + (size_t)n * D + d0;
#pragma unroll 4
        for (int k = 0; k < KC; k += 4) {
            float4 wv = *reinterpret_cast<const float4*>(wrow + k);
            unsigned long long wp0 = pack2(wv.x, wv.y);
            unsigned long long wp1 = pack2(wv.z, wv.w);
#pragma unroll
            for (int bi = 0; bi < 16; bi++) {
                ulonglong2 av = *reinterpret_cast<const ulonglong2*>(
                    zrow_base + (size_t)bi * KC + k);
                acc[bi] = fma2(wp0, av.x, acc[bi]);
                acc[bi] = fma2(wp1, av.y, acc[bi]);
            }
        }
        __syncthreads();
    }

    // ================= epilogue =================
    const float rbn = rb[n];
    const float bterm = bias_diag[n] * gates[o];   // bias_diag flat index == n
#pragma unroll
    for (int bi = 0; bi < 16; bi++) {
        int b = g * 16 + bi;
        float lo, hi;
        unpack2(acc[bi], lo, hi);
        size_t idx = (size_t)b * NN + n;
        float zp = lo + hi + rbn + bterm
                 - 0.8f * Fstate[idx] - 0.4f * Z[idx];
        g_znew[idx] = tanhf(zp);
    }
}

// ---------- Kernel 3: output projection (N=11) ----------
__global__ void out_kernel(const float* __restrict__ out_w,   // [11, N]
                           const float* __restrict__ out_b,   // [11]
                           float* __restrict__ out)           // [B, 11]
{
    int b = blockIdx.x;
    int t = threadIdx.x;
    float p[11];
#pragma unroll
    for (int j = 0; j < 11; j++) p[j] = 0.f;

    for (int n = t; n < NN; n += 256) {
        float z = g_znew[(size_t)b * NN + n];
#pragma unroll
        for (int j = 0; j < 11; j++) p[j] += z * out_w[(size_t)j * NN + n];
    }

    __shared__ float red[11 * 256];
#pragma unroll
    for (int j = 0; j < 11; j++) red[j * 256 + t] = p[j];
    __syncthreads();
    for (int st = 128; st > 0; st >>= 1) {
        if (t < st) {
#pragma unroll
            for (int j = 0; j < 11; j++) red[j * 256 + t] += red[j * 256 + t + st];
        }
        __syncthreads();
    }
    if (t < 11) {
        float r = red[t * 256] + out_b[t];
        out[(size_t)b * 11 + t] = (t < 10) ? r : 1.0f / (1.0f + expf(-r));
    }
}

// ---------- launch ----------
extern "C" void kernel_launch(void* const* d_in, const int* in_sizes, int n_in,
                              void* d_out, int out_size) {
    const float* x        = (const float*)d_in[0];   // (64, 3072)
    const float* Z        = (const float*)d_in[1];   // (64, 4, 2048)
    const float* Fstate   = (const float*)d_in[2];   // (64, 4, 2048)
    const float* rw       = (const float*)d_in[3];   // (8192, 3072)
    const float* rb       = (const float*)d_in[4];   // (8192,)
    const float* W        = (const float*)d_in[5];   // (4,4,2048,2048)
    const float* Wmask    = (const float*)d_in[6];   // (4,4,2048,2048)
    const float* bias_d   = (const float*)d_in[7];   // (4,2048)
    const float* out_w    = (const float*)d_in[8];   // (11, 8192)
    const float* out_b    = (const float*)d_in[9];   // (11,)
    // d_in[10] = area_idx (arange, identity scatter) — unused
    float* out = (float*)d_out;                      // (64, 11)

    gate_kernel<<<NA, 256>>>(Z);
    main_kernel<<<NN / 64, 256>>>(x, Z, Fstate, rw, rb, W, Wmask, bias_d);
    out_kernel<<<B, 256>>>(out_w, out_b, out);
}

// round 3
// speedup vs baseline: 2.8090x; 2.8090x over previous
#include <cuda_runtime.h>
#include <cstdint>
#include <cstddef>

#define NB 64
#define NTOT 8192
#define THRESH 0.02f
#define CHUNK 32
#define WS_STRIDE 260                       // floats per k-row of W tile
#define ZS_STRIDE 68                        // float2 per k-row of z tile
#define WS_BYTES (CHUNK * WS_STRIDE * 4)    // 33280
#define ZS_BYTES (CHUNK * ZS_STRIDE * 8)    // 17408
#define BUF_BYTES (WS_BYTES + ZS_BYTES)     // 50688
#define SMEM_TOTAL (2 * BUF_BYTES)          // 101376

__device__ float g_gatesum[4];
__device__ float g_accum[NB * NTOT];
__device__ float g_znew[NB * NTOT];

static __device__ __forceinline__ unsigned long long fma2(unsigned long long a,
                                                          unsigned long long b,
                                                          unsigned long long c) {
    unsigned long long d;
    asm("fma.rn.f32x2 %0, %1, %2, %3;" : "=l"(d) : "l"(a), "l"(b), "l"(c));
    return d;
}
static __device__ __forceinline__ void unpack2(unsigned long long v, float& lo, float& hi) {
    asm("mov.b64 {%0, %1}, %2;" : "=f"(lo), "=f"(hi) : "l"(v));
}

// ---------------- zero ----------------
__global__ void zero_kernel() {
    int idx = blockIdx.x * 256 + threadIdx.x;        // 128 blocks -> 32768 threads
    float4* p = (float4*)g_accum;
#pragma unroll
    for (int j = 0; j < 4; j++) p[idx * 4 + j] = make_float4(0.f, 0.f, 0.f, 0.f);
    if (blockIdx.x == 0 && threadIdx.x < 4) g_gatesum[threadIdx.x] = 0.f;
}

// ---------------- gate ----------------
__global__ void gate_kernel(const float* __restrict__ Z) {
    int area = blockIdx.x & 3;
    int slice = blockIdx.x >> 2;          // 16 slices of 4 batches
    int t = threadIdx.x;
    float s = 0.f;
#pragma unroll
    for (int it = 0; it < 8; it++) {
        int f = t + 256 * it;             // 2048 float4 per block
        int b = slice * 4 + (f >> 9);
        int a4 = f & 511;
        float4 v = *(const float4*)(Z + (size_t)b * NTOT + (size_t)area * 2048 + a4 * 4);
        s += fabsf(v.x) + fabsf(v.y) + fabsf(v.z) + fabsf(v.w);
    }
#pragma unroll
    for (int o = 16; o; o >>= 1) s += __shfl_xor_sync(0xffffffffu, s, o);
    __shared__ float ws[8];
    if ((t & 31) == 0) ws[t >> 5] = s;
    __syncthreads();
    if (t == 0) {
        float tot = 0.f;
        for (int w = 0; w < 8; w++) tot += ws[w];
        atomicAdd(&g_gatesum[area], tot);
    }
}

// ---------------- main: einsum + stim partials ----------------
__global__ __launch_bounds__(256, 1)
void main_kernel(const float* __restrict__ x, const float* __restrict__ Z,
                 const float* __restrict__ rw, const float* __restrict__ W,
                 const float* __restrict__ Mk)
{
    extern __shared__ char smem[];
    const int t = threadIdx.x;
    const int tc = t & 31;
    const int tr = t >> 5;
    const int bid = blockIdx.x;
    const bool stim = (bid >= 512);

    const float* wsrc;
    const float* msrc = nullptr;
    const float* zsrc;
    int n0, ldw, zstr;
    float scale = 1.f;

    if (!stim) {
        int ct = bid >> 4, ks = bid & 15;
        int i = ks >> 2;
        int o = ct >> 3;
        int u0 = (ct & 7) * 256;
        int kb = (ks & 3) * 512;
        n0 = ct * 256;
        ldw = 2048; zstr = NTOT;
        wsrc = W  + ((size_t)(o * 4 + i) * 2048 + u0) * 2048 + kb;
        msrc = Mk + ((size_t)(o * 4 + i) * 2048 + u0) * 2048 + kb;
        zsrc = Z + (size_t)i * 2048 + kb;
        scale = (g_gatesum[i] * (1.0f / 131072.0f) > THRESH) ? 1.f : 0.f;
    } else {
        int sb = bid - 512;
        int ct = sb / 6, ks = sb - ct * 6;
        n0 = ct * 256;
        ldw = 3072; zstr = 3072;
        wsrc = rw + (size_t)n0 * 3072 + ks * 512;
        zsrc = x + ks * 512;
    }

    unsigned long long acc[32];
#pragma unroll
    for (int i = 0; i < 32; i++) acc[i] = 0ULL;

    float4 rwv[8], rmv[8], rzv[2];

    auto ldg_chunk = [&](int c) {
        int k0 = c * CHUNK;
#pragma unroll
        for (int it = 0; it < 8; it++) {
            int f = t + 256 * it;
            int col = f >> 3, kq = f & 7;
            const float* p = wsrc + (size_t)col * ldw + k0 + kq * 4;
            rwv[it] = *(const float4*)p;
            if (!stim)
                rmv[it] = *(const float4*)(msrc + (size_t)col * ldw + k0 + kq * 4);
        }
#pragma unroll
        for (int it = 0; it < 2; it++) {
            int f = t + 256 * it;
            int b = f >> 3, kq = f & 7;
            rzv[it] = *(const float4*)(zsrc + (size_t)b * zstr + k0 + kq * 4);
        }
    };
    auto sts_chunk = [&](char* buf) {
        float* ws = (float*)buf;
        float2* zs = (float2*)(buf + WS_BYTES);
#pragma unroll
        for (int it = 0; it < 8; it++) {
            int f = t + 256 * it;
            int col = f >> 3, kq = f & 7;
            float4 w = rwv[it];
            if (!stim) {
                float4 m = rmv[it];
                w.x *= __saturatef(m.x); w.y *= __saturatef(m.y);
                w.z *= __saturatef(m.z); w.w *= __saturatef(m.w);
            }
            ws[(kq * 4 + 0) * WS_STRIDE + col] = w.x;
            ws[(kq * 4 + 1) * WS_STRIDE + col] = w.y;
            ws[(kq * 4 + 2) * WS_STRIDE + col] = w.z;
            ws[(kq * 4 + 3) * WS_STRIDE + col] = w.w;
        }
#pragma unroll
        for (int it = 0; it < 2; it++) {
            int f = t + 256 * it;
            int b = f >> 3, kq = f & 7;
            float4 z = rzv[it];
            zs[(kq * 4 + 0) * ZS_STRIDE + b] = make_float2(z.x, z.x);
            zs[(kq * 4 + 1) * ZS_STRIDE + b] = make_float2(z.y, z.y);
            zs[(kq * 4 + 2) * ZS_STRIDE + b] = make_float2(z.z, z.z);
            zs[(kq * 4 + 3) * ZS_STRIDE + b] = make_float2(z.w, z.w);
        }
    };
    auto compute_chunk = [&](const char* buf) {
        const float* ws = (const float*)buf;
        const char* zb = buf + WS_BYTES;
#pragma unroll
        for (int k = 0; k < CHUNK; k++) {
            ulonglong2 wv0 = *(const ulonglong2*)(ws + k * WS_STRIDE + tc * 4);
            ulonglong2 wv1 = *(const ulonglong2*)(ws + k * WS_STRIDE + 128 + tc * 4);
#pragma unroll
            for (int s = 0; s < 4; s++) {
                ulonglong2 zd = *(const ulonglong2*)(zb + (size_t)k * (ZS_STRIDE * 8)
                                                        + (size_t)(tr * 8 + 2 * s) * 8);
                acc[(2*s  )*4+0] = fma2(zd.x, wv0.x, acc[(2*s  )*4+0]);
                acc[(2*s  )*4+1] = fma2(zd.x, wv0.y, acc[(2*s  )*4+1]);
                acc[(2*s  )*4+2] = fma2(zd.x, wv1.x, acc[(2*s  )*4+2]);
                acc[(2*s  )*4+3] = fma2(zd.x, wv1.y, acc[(2*s  )*4+3]);
                acc[(2*s+1)*4+0] = fma2(zd.y, wv0.x, acc[(2*s+1)*4+0]);
                acc[(2*s+1)*4+1] = fma2(zd.y, wv0.y, acc[(2*s+1)*4+1]);
                acc[(2*s+1)*4+2] = fma2(zd.y, wv1.x, acc[(2*s+1)*4+2]);
                acc[(2*s+1)*4+3] = fma2(zd.y, wv1.y, acc[(2*s+1)*4+3]);
            }
        }
    };

    ldg_chunk(0);
    sts_chunk(smem);
    __syncthreads();
    for (int c = 0; c < 16; c++) {
        if (c + 1 < 16) ldg_chunk(c + 1);
        compute_chunk(smem + (size_t)(c & 1) * BUF_BYTES);
        if (c + 1 < 16) sts_chunk(smem + (size_t)((c + 1) & 1) * BUF_BYTES);
        __syncthreads();
    }

    if (scale != 0.f) {
#pragma unroll
        for (int bb = 0; bb < 8; bb++) {
            int b = tr * 8 + bb;
#pragma unroll
            for (int p = 0; p < 4; p++) {
                float lo, hi;
                unpack2(acc[bb * 4 + p], lo, hi);
                int col = (p < 2) ? (4 * tc + 2 * p) : (128 + 4 * tc + 2 * (p - 2));
                atomicAdd(&g_accum[(size_t)b * NTOT + n0 + col],     lo * scale);
                atomicAdd(&g_accum[(size_t)b * NTOT + n0 + col + 1], hi * scale);
            }
        }
    }
}

// ---------------- combine: bias/decay/tanh ----------------
__global__ void combine_kernel(const float* __restrict__ Z, const float* __restrict__ F,
                               const float* __restrict__ rb, const float* __restrict__ bias)
{
    int idx = blockIdx.x * 256 + threadIdx.x;       // float4 index, 131072 total
    int rest = idx & 2047;
    int n4 = rest * 4;
    int o = n4 >> 11;
    float g = (g_gatesum[o] * (1.0f / 131072.0f) > THRESH) ? 1.f : 0.f;
    float4 a  = ((const float4*)g_accum)[idx];
    float4 rv = *(const float4*)(rb + n4);
    float4 bv = *(const float4*)(bias + n4);
    float4 Fv = ((const float4*)F)[idx];
    float4 Zv = ((const float4*)Z)[idx];
    float4 out;
    out.x = tanhf(a.x + rv.x + bv.x * g - 0.8f * Fv.x - 0.4f * Zv.x);
    out.y = tanhf(a.y + rv.y + bv.y * g - 0.8f * Fv.y - 0.4f * Zv.y);
    out.z = tanhf(a.z + rv.z + bv.z * g - 0.8f * Fv.z - 0.4f * Zv.z);
    out.w = tanhf(a.w + rv.w + bv.w * g - 0.8f * Fv.w - 0.4f * Zv.w);
    ((float4*)g_znew)[idx] = out;
}

// ---------------- output projection ----------------
__global__ void out_kernel(const float* __restrict__ out_w, const float* __restrict__ out_b,
                           float* __restrict__ out)
{
    int b = blockIdx.x;
    int t = threadIdx.x;
    float p[11];
#pragma unroll
    for (int j = 0; j < 11; j++) p[j] = 0.f;
    const float4* zr = (const float4*)(g_znew + (size_t)b * NTOT);
#pragma unroll
    for (int it = 0; it < 8; it++) {
        int f4 = t + 256 * it;
        float4 z = zr[f4];
#pragma unroll
        for (int j = 0; j < 11; j++) {
            float4 w = ((const float4*)(out_w + (size_t)j * NTOT))[f4];
            p[j] += z.x * w.x + z.y * w.y + z.z * w.z + z.w * w.w;
        }
    }
    __shared__ float red[11 * 64];
#pragma unroll
    for (int j = 0; j < 11; j++) {
        float v = p[j];
#pragma unroll
        for (int o = 16; o; o >>= 1) v += __shfl_xor_sync(0xffffffffu, v, o);
        if ((t & 31) == 0) red[j * 64 + (t >> 5)] = v;
    }
    __syncthreads();
    if (t < 11) {
        float r = out_b[t];
        for (int w = 0; w < 8; w++) r += red[t * 64 + w];
        out[(size_t)b * 11 + t] = (t < 10) ? r : 1.0f / (1.0f + expf(-r));
    }
}

// ---------------- launch ----------------
extern "C" void kernel_launch(void* const* d_in, const int* in_sizes, int n_in,
                              void* d_out, int out_size) {
    const float* x      = (const float*)d_in[0];
    const float* Z      = (const float*)d_in[1];
    const float* Fstate = (const float*)d_in[2];
    const float* rw     = (const float*)d_in[3];
    const float* rb     = (const float*)d_in[4];
    const float* W      = (const float*)d_in[5];
    const float* Mk     = (const float*)d_in[6];
    const float* bias_d = (const float*)d_in[7];
    const float* out_w  = (const float*)d_in[8];
    const float* out_b  = (const float*)d_in[9];
    float* out = (float*)d_out;

    cudaFuncSetAttribute(main_kernel, cudaFuncAttributeMaxDynamicSharedMemorySize, SMEM_TOTAL);

    zero_kernel<<<128, 256>>>();
    gate_kernel<<<64, 256>>>(Z);
    main_kernel<<<704, 256, SMEM_TOTAL>>>(x, Z, rw, W, Mk);
    combine_kernel<<<512, 256>>>(Z, Fstate, rb, bias_d);
    out_kernel<<<NB, 256>>>(out_w, out_b, out);
}

// round 5
// speedup vs baseline: 3.1560x; 1.1235x over previous
#include <cuda_runtime.h>
#include <cuda_bf16.h>
#include <cstdint>
#include <cstddef>

#define NBATCH 64
#define NTOT   8192
#define THRESH 0.02f
#define KT     64
#define NCH_E  128                 // einsum chunks (K=8192)
#define NCH    176                 // + 48 stim chunks (K=3072)
#define HALF   88                  // chunks per k-slice
#define MTILE  128

// smem per buffer: Ahi 16K | Alo 16K | Bhi 8K | Blo 8K  (SW128, 128B rows)
#define WHI_OFF 0
#define WLO_OFF 16384
#define ZHI_OFF 32768
#define ZLO_OFF 40960
#define BUFB    49152
#define SMEM_TOTAL (2 * BUFB)      // 98304

__device__ float g_gatesum[4];
__device__ float g_accum[NBATCH * NTOT];
__device__ float g_znew[NBATCH * NTOT];

// ---------------- helpers ----------------
static __device__ __forceinline__ uint32_t smem_u32(const void* p) {
    uint32_t a;
    asm("{ .reg .u64 t; cvta.to.shared.u64 t, %1; cvt.u32.u64 %0, t; }" : "=r"(a) : "l"(p));
    return a;
}
#define SWZ(o) ((o) ^ (((o) >> 3) & 0x70))

static __device__ __forceinline__ void ldsm4(uint32_t* r, uint32_t addr) {
    asm volatile("ldmatrix.sync.aligned.m8n8.x4.shared.b16 {%0,%1,%2,%3}, [%4];"
                 : "=r"(r[0]), "=r"(r[1]), "=r"(r[2]), "=r"(r[3]) : "r"(addr));
}
static __device__ __forceinline__ void mma_bf16(float* d, const uint32_t* a,
                                                uint32_t b0, uint32_t b1) {
    asm volatile("mma.sync.aligned.m16n8k16.row.col.f32.bf16.bf16.f32 "
                 "{%0,%1,%2,%3}, {%4,%5,%6,%7}, {%8,%9}, {%0,%1,%2,%3};"
                 : "+f"(d[0]), "+f"(d[1]), "+f"(d[2]), "+f"(d[3])
                 : "r"(a[0]), "r"(a[1]), "r"(a[2]), "r"(a[3]), "r"(b0), "r"(b1));
}

// split 8 floats into packed bf16 hi/lo quads
static __device__ __forceinline__ void split8(const float* f, uint4& hp, uint4& lp) {
    uint32_t h[4], l[4];
#pragma unroll
    for (int j = 0; j < 4; j++) {
        float a = f[2 * j], b = f[2 * j + 1];
        __nv_bfloat16 ha = __float2bfloat16_rn(a), hb = __float2bfloat16_rn(b);
        float la = a - __bfloat162float(ha);
        float lb = b - __bfloat162float(hb);
        __nv_bfloat162 hh = __halves2bfloat162(ha, hb);
        __nv_bfloat162 ll = __halves2bfloat162(__float2bfloat16_rn(la), __float2bfloat16_rn(lb));
        h[j] = *reinterpret_cast<uint32_t*>(&hh);
        l[j] = *reinterpret_cast<uint32_t*>(&ll);
    }
    hp = make_uint4(h[0], h[1], h[2], h[3]);
    lp = make_uint4(l[0], l[1], l[2], l[3]);
}

// ---------------- zero + gate ----------------
__global__ void zero_kernel() {
    int idx = blockIdx.x * 256 + threadIdx.x;
    float4* p = (float4*)g_accum;
#pragma unroll
    for (int j = 0; j < 4; j++) p[idx * 4 + j] = make_float4(0.f, 0.f, 0.f, 0.f);
    if (blockIdx.x == 0 && threadIdx.x < 4) g_gatesum[threadIdx.x] = 0.f;
}

__global__ void gate_kernel(const float* __restrict__ Z) {
    int area = blockIdx.x & 3, slice = blockIdx.x >> 2, t = threadIdx.x;
    float s = 0.f;
#pragma unroll
    for (int it = 0; it < 8; it++) {
        int f = t + 256 * it;
        int b = slice * 4 + (f >> 9), a4 = f & 511;
        float4 v = *(const float4*)(Z + (size_t)b * NTOT + (size_t)area * 2048 + a4 * 4);
        s += fabsf(v.x) + fabsf(v.y) + fabsf(v.z) + fabsf(v.w);
    }
#pragma unroll
    for (int o = 16; o; o >>= 1) s += __shfl_xor_sync(0xffffffffu, s, o);
    __shared__ float ws[8];
    if ((t & 31) == 0) ws[t >> 5] = s;
    __syncthreads();
    if (t == 0) {
        float tot = 0.f;
        for (int w = 0; w < 8; w++) tot += ws[w];
        atomicAdd(&g_gatesum[area], tot);
    }
}

// ---------------- main HMMA kernel ----------------
__global__ __launch_bounds__(256, 1)
void main_kernel(const float* __restrict__ x, const float* __restrict__ Z,
                 const float* __restrict__ rw, const float* __restrict__ W,
                 const float* __restrict__ Mk)
{
    extern __shared__ char smem[];
    const uint32_t sb = smem_u32(smem);
    const int t = threadIdx.x, wid = t >> 5, lid = t & 31;
    const int ct = blockIdx.x >> 1;         // M-tile 0..63
    const int ks = blockIdx.x & 1;          // k-slice
    const int n0 = ct * MTILE;
    const int o = ct >> 4;
    const int u0 = (ct & 15) * MTILE;

    float gates[4];
#pragma unroll
    for (int i = 0; i < 4; i++)
        gates[i] = (g_gatesum[i] * (1.0f / 131072.0f) > THRESH) ? 1.f : 0.f;

    // loader indices
    const int ar = t >> 1, ah = t & 1;      // A: row 0..127, k-half
    const int zb = t >> 2, zq = t & 3;      // B: batch 0..63, k-quarter

    float4 wv[8], mv[8], zv[4];
    uint4 apk_h[4], apk_l[4], zpk_h[2], zpk_l[2];

    auto ldg = [&](int c) {
        if (c < NCH_E) {
            int k0 = c * KT, i = k0 >> 11, kl = k0 & 2047;
            const float* wr = W  + ((size_t)(o * 4 + i) * 2048 + u0 + ar) * 2048 + kl + ah * 32;
            const float* mr = Mk + ((size_t)(o * 4 + i) * 2048 + u0 + ar) * 2048 + kl + ah * 32;
#pragma unroll
            for (int j = 0; j < 8; j++) {
                wv[j] = *(const float4*)(wr + j * 4);
                mv[j] = *(const float4*)(mr + j * 4);
            }
            const float* zr = Z + (size_t)zb * NTOT + k0 + zq * 16;
#pragma unroll
            for (int j = 0; j < 4; j++) zv[j] = *(const float4*)(zr + j * 4);
        } else {
            int k0 = (c - NCH_E) * KT;
            const float* wr = rw + (size_t)(n0 + ar) * 3072 + k0 + ah * 32;
#pragma unroll
            for (int j = 0; j < 8; j++) wv[j] = *(const float4*)(wr + j * 4);
            const float* zr = x + (size_t)zb * 3072 + k0 + zq * 16;
#pragma unroll
            for (int j = 0; j < 4; j++) zv[j] = *(const float4*)(zr + j * 4);
        }
    };

    auto cvt = [&](int c) {
        const bool einsum = (c < NCH_E);
        const float zg = einsum ? gates[(c * KT) >> 11] : 1.f;
        float f[8];
#pragma unroll
        for (int g = 0; g < 4; g++) {
            float4 a = wv[2 * g], b = wv[2 * g + 1];
            f[0] = a.x; f[1] = a.y; f[2] = a.z; f[3] = a.w;
            f[4] = b.x; f[5] = b.y; f[6] = b.z; f[7] = b.w;
            if (einsum) {
                float4 ma = mv[2 * g], mb = mv[2 * g + 1];
                f[0] *= __saturatef(ma.x); f[1] *= __saturatef(ma.y);
                f[2] *= __saturatef(ma.z); f[3] *= __saturatef(ma.w);
                f[4] *= __saturatef(mb.x); f[5] *= __saturatef(mb.y);
                f[6] *= __saturatef(mb.z); f[7] *= __saturatef(mb.w);
            }
            split8(f, apk_h[g], apk_l[g]);
        }
#pragma unroll
        for (int g = 0; g < 2; g++) {
            float4 a = zv[2 * g], b = zv[2 * g + 1];
            f[0] = a.x * zg; f[1] = a.y * zg; f[2] = a.z * zg; f[3] = a.w * zg;
            f[4] = b.x * zg; f[5] = b.y * zg; f[6] = b.z * zg; f[7] = b.w * zg;
            split8(f, zpk_h[g], zpk_l[g]);
        }
    };

    auto sts = [&](uint32_t buf) {
#pragma unroll
        for (int g = 0; g < 4; g++) {
            uint32_t sw = SWZ((uint32_t)(ar * 128 + ah * 64 + g * 16));
            asm volatile("st.shared.v4.b32 [%0], {%1,%2,%3,%4};" ::
                         "r"(buf + WHI_OFF + sw),
                         "r"(apk_h[g].x), "r"(apk_h[g].y), "r"(apk_h[g].z), "r"(apk_h[g].w) : "memory");
            asm volatile("st.shared.v4.b32 [%0], {%1,%2,%3,%4};" ::
                         "r"(buf + WLO_OFF + sw),
                         "r"(apk_l[g].x), "r"(apk_l[g].y), "r"(apk_l[g].z), "r"(apk_l[g].w) : "memory");
        }
#pragma unroll
        for (int g = 0; g < 2; g++) {
            uint32_t sw = SWZ((uint32_t)(zb * 128 + zq * 32 + g * 16));
            asm volatile("st.shared.v4.b32 [%0], {%1,%2,%3,%4};" ::
                         "r"(buf + ZHI_OFF + sw),
                         "r"(zpk_h[g].x), "r"(zpk_h[g].y), "r"(zpk_h[g].z), "r"(zpk_h[g].w) : "memory");
            asm volatile("st.shared.v4.b32 [%0], {%1,%2,%3,%4};" ::
                         "r"(buf + ZLO_OFF + sw),
                         "r"(zpk_l[g].x), "r"(zpk_l[g].y), "r"(zpk_l[g].z), "r"(zpk_l[g].w) : "memory");
        }
    };

    // warp tile: mw in 0..3 (32 cols), nw in 0..1 (32 batches)
    const int mw = wid & 3, nw = wid >> 2;
    const int lr = lid & 15, lh = lid >> 4;
    const uint32_t a_row0 = (uint32_t)((mw * 32 + lr) * 128 + lh * 16);
    const uint32_t a_row1 = a_row0 + 16 * 128;
    const uint32_t b_row0 = (uint32_t)((nw * 32 + lr) * 128 + lh * 16);
    const uint32_t b_row1 = b_row0 + 16 * 128;

    float acc[8][4];
#pragma unroll
    for (int i = 0; i < 8; i++)
#pragma unroll
        for (int j = 0; j < 4; j++) acc[i][j] = 0.f;

    auto mma_chunk = [&](uint32_t buf) {
#pragma unroll
        for (int kk = 0; kk < 4; kk++) {
            const uint32_t ko = kk * 32;
            uint32_t ah0[4], ah1[4], al0[4], al1[4];
            ldsm4(ah0, buf + WHI_OFF + SWZ(a_row0 + ko));
            ldsm4(ah1, buf + WHI_OFF + SWZ(a_row1 + ko));
            ldsm4(al0, buf + WLO_OFF + SWZ(a_row0 + ko));
            ldsm4(al1, buf + WLO_OFF + SWZ(a_row1 + ko));
            uint32_t bh0[4], bh1[4], bl0[4], bl1[4];
            ldsm4(bh0, buf + ZHI_OFF + SWZ(b_row0 + ko));
            ldsm4(bh1, buf + ZHI_OFF + SWZ(b_row1 + ko));
            ldsm4(bl0, buf + ZLO_OFF + SWZ(b_row0 + ko));
            ldsm4(bl1, buf + ZLO_OFF + SWZ(b_row1 + ko));
#pragma unroll
            for (int nt = 0; nt < 4; nt++) {
                const uint32_t* bh = (nt < 2) ? bh0 : bh1;
                const uint32_t* bl = (nt < 2) ? bl0 : bl1;
                const int j = nt & 1;
                mma_bf16(acc[nt],     ah0, bh[j], bh[j + 2]);
                mma_bf16(acc[nt],     ah0, bl[j], bl[j + 2]);
                mma_bf16(acc[nt],     al0, bh[j], bh[j + 2]);
                mma_bf16(acc[4 + nt], ah1, bh[j], bh[j + 2]);
                mma_bf16(acc[4 + nt], ah1, bl[j], bl[j + 2]);
                mma_bf16(acc[4 + nt], al1, bh[j], bh[j + 2]);
            }
        }
    };

    const int c0 = ks * HALF, c1 = c0 + HALF;
    ldg(c0);
    cvt(c0);
    sts(sb);
    __syncthreads();
    for (int c = c0; c < c1; c++) {
        const int p = (c - c0) & 1;
        if (c + 1 < c1) ldg(c + 1);
        mma_chunk(sb + (uint32_t)p * BUFB);
        if (c + 1 < c1) { cvt(c + 1); sts(sb + (uint32_t)(p ^ 1) * BUFB); }
        __syncthreads();
    }

    // epilogue: spread atomics into g_accum
    const int mbase = n0 + mw * 32;
    const int nbase = nw * 32;
    const int r = lid >> 2, cp = (lid & 3) * 2;
#pragma unroll
    for (int mt = 0; mt < 2; mt++) {
#pragma unroll
        for (int nt = 0; nt < 4; nt++) {
            const float* cc = acc[mt * 4 + nt];
            int m = mbase + mt * 16 + r;
            int nb = nbase + nt * 8 + cp;
            atomicAdd(&g_accum[(size_t)nb * NTOT + m],           cc[0]);
            atomicAdd(&g_accum[(size_t)(nb + 1) * NTOT + m],     cc[1]);
            atomicAdd(&g_accum[(size_t)nb * NTOT + m + 8],       cc[2]);
            atomicAdd(&g_accum[(size_t)(nb + 1) * NTOT + m + 8], cc[3]);
        }
    }
}

// ---------------- combine: bias/decay/tanh ----------------
__global__ void combine_kernel(const float* __restrict__ Z, const float* __restrict__ F,
                               const float* __restrict__ rb, const float* __restrict__ bias)
{
    int idx = blockIdx.x * 256 + threadIdx.x;
    int rest = idx & 2047;
    int n4 = rest * 4;
    int o = n4 >> 11;
    float g = (g_gatesum[o] * (1.0f / 131072.0f) > THRESH) ? 1.f : 0.f;
    float4 a  = ((const float4*)g_accum)[idx];
    float4 rv = *(const float4*)(rb + n4);
    float4 bv = *(const float4*)(bias + n4);
    float4 Fv = ((const float4*)F)[idx];
    float4 Zv = ((const float4*)Z)[idx];
    float4 outv;
    outv.x = tanhf(a.x + rv.x + bv.x * g - 0.8f * Fv.x - 0.4f * Zv.x);
    outv.y = tanhf(a.y + rv.y + bv.y * g - 0.8f * Fv.y - 0.4f * Zv.y);
    outv.z = tanhf(a.z + rv.z + bv.z * g - 0.8f * Fv.z - 0.4f * Zv.z);
    outv.w = tanhf(a.w + rv.w + bv.w * g - 0.8f * Fv.w - 0.4f * Zv.w);
    ((float4*)g_znew)[idx] = outv;
}

// ---------------- output projection ----------------
__global__ void out_kernel(const float* __restrict__ out_w, const float* __restrict__ out_b,
                           float* __restrict__ out)
{
    int b = blockIdx.x, t = threadIdx.x;
    float p[11];
#pragma unroll
    for (int j = 0; j < 11; j++) p[j] = 0.f;
    const float4* zr = (const float4*)(g_znew + (size_t)b * NTOT);
#pragma unroll
    for (int it = 0; it < 8; it++) {
        int f4 = t + 256 * it;
        float4 z = zr[f4];
#pragma unroll
        for (int j = 0; j < 11; j++) {
            float4 w = ((const float4*)(out_w + (size_t)j * NTOT))[f4];
            p[j] += z.x * w.x + z.y * w.y + z.z * w.z + z.w * w.w;
        }
    }
    __shared__ float red[11 * 64];
#pragma unroll
    for (int j = 0; j < 11; j++) {
        float v = p[j];
#pragma unroll
        for (int o = 16; o; o >>= 1) v += __shfl_xor_sync(0xffffffffu, v, o);
        if ((t & 31) == 0) red[j * 64 + (t >> 5)] = v;
    }
    __syncthreads();
    if (t < 11) {
        float r = out_b[t];
        for (int w = 0; w < 8; w++) r += red[t * 64 + w];
        out[(size_t)b * 11 + t] = (t < 10) ? r : 1.0f / (1.0f + expf(-r));
    }
}

// ---------------- launch ----------------
extern "C" void kernel_launch(void* const* d_in, const int* in_sizes, int n_in,
                              void* d_out, int out_size) {
    const float* x      = (const float*)d_in[0];
    const float* Z      = (const float*)d_in[1];
    const float* Fstate = (const float*)d_in[2];
    const float* rw     = (const float*)d_in[3];
    const float* rb     = (const float*)d_in[4];
    const float* W      = (const float*)d_in[5];
    const float* Mk     = (const float*)d_in[6];
    const float* bias_d = (const float*)d_in[7];
    const float* out_w  = (const float*)d_in[8];
    const float* out_b  = (const float*)d_in[9];
    float* out = (float*)d_out;

    cudaFuncSetAttribute(main_kernel, cudaFuncAttributeMaxDynamicSharedMemorySize, SMEM_TOTAL);

    zero_kernel<<<128, 256>>>();
    gate_kernel<<<64, 256>>>(Z);
    main_kernel<<<128, 256, SMEM_TOTAL>>>(x, Z, rw, W, Mk);
    combine_kernel<<<512, 256>>>(Z, Fstate, rb, bias_d);
    out_kernel<<<NBATCH, 256>>>(out_w, out_b, out);
}